// round 9
// baseline (speedup 1.0000x reference)
#include <cuda_runtime.h>
#include <cuda_fp16.h>
#include <cstddef>

#define TT 1024
#define BB 16
#define CC 64
#define BIGF 1e10f
// 1/(gamma*ln2), gamma = 0.01
#define KS 144.2695040888963f
// gamma*ln2
#define GLN2 0.006931471805599453f
// (med - min) threshold below which exp terms matter (16 / KS)
#define GAPT 0.11090354888959125f

// Scratch (device globals: allocation-free rule)
// fp16 pair-interleaved diag-major cost:
//   slab row rr = i+j-2 (0-based 0..2046), col = i-1.
//   element index = ((b<<20) + ((rr>>1)<<10) + col)*2 + (rr&1)
__device__ __half g_costh[(size_t)BB * 1024 * 1024 * 2];   // 67 MB
__device__ float g_nx[BB * TT];
__device__ float g_ny[BB * TT];
__device__ float g_partial[BB];

__device__ __forceinline__ float ex2f(float x) {
    float y;
    asm("ex2.approx.ftz.f32 %0, %1;" : "=f"(y) : "f"(x));
    return y;
}
__device__ __forceinline__ float lg2f(float x) {
    float y;
    asm("lg2.approx.ftz.f32 %0, %1;" : "=f"(y) : "f"(x));
    return y;
}

// ---------------------------------------------------------------------------
// Kernel 0: row norms  ||x_i||^2, ||y_j||^2  (one warp per row)
// ---------------------------------------------------------------------------
__global__ void norms_kernel(const float* __restrict__ x,
                             const float* __restrict__ y) {
    int gwarp = (blockIdx.x * blockDim.x + threadIdx.x) >> 5;
    int lane = threadIdx.x & 31;
    const int nrows = BB * TT;
    if (gwarp >= 2 * nrows) return;
    const float* src = (gwarp < nrows) ? x : y;
    float* dst = (gwarp < nrows) ? g_nx : g_ny;
    int row = (gwarp < nrows) ? gwarp : (gwarp - nrows);
    float v0 = src[(size_t)row * CC + lane];
    float v1 = src[(size_t)row * CC + 32 + lane];
    float s = v0 * v0 + v1 * v1;
    #pragma unroll
    for (int o = 16; o; o >>= 1) s += __shfl_xor_sync(0xFFFFFFFFu, s, o);
    if (lane == 0) dst[row] = s;
}

// ---------------------------------------------------------------------------
// Kernel 1: cost tile 128x128 per CTA (8x8 regs/thread), then scatter the
// tile (fp16) to pair-interleaved diag-major g_costh via smem.
// ---------------------------------------------------------------------------
#define PITCH 132
__global__ __launch_bounds__(256) void cost_kernel(const float* __restrict__ x,
                                                   const float* __restrict__ y) {
    __shared__ float sbuf[8448];   // union: xs[32*132] + ys[32*132] | tile 64*132
    float* xs = sbuf;              // [kk][row] -> kk*132 + row
    float* ys = sbuf + 4224;

    int b = blockIdx.z;
    int I0 = blockIdx.y * 128;
    int J0 = blockIdx.x * 128;
    int tid = threadIdx.x;
    int tx = tid & 15;
    int ty = tid >> 4;
    int w = tid >> 5;
    int lane = tid & 31;

    const float* xb = x + ((size_t)b * TT + I0) * CC;
    const float* yb = y + ((size_t)b * TT + J0) * CC;

    float acc[8][8];
    #pragma unroll
    for (int r = 0; r < 8; r++)
        #pragma unroll
        for (int s = 0; s < 8; s++) acc[r][s] = 0.f;

    for (int k0 = 0; k0 < CC; k0 += 32) {
        __syncthreads();
        #pragma unroll
        for (int e = 0; e < 4096; e += 256) {
            int idx = e + tid;
            int row = idx >> 5;
            int kk = idx & 31;
            xs[kk * 132 + row] = xb[(size_t)row * CC + k0 + kk];
            ys[kk * 132 + row] = yb[(size_t)row * CC + k0 + kk];
        }
        __syncthreads();
        #pragma unroll
        for (int kk = 0; kk < 32; kk++) {
            float4 xv0 = *(const float4*)&xs[kk * 132 + ty * 8];
            float4 xv1 = *(const float4*)&xs[kk * 132 + ty * 8 + 4];
            float4 yv0 = *(const float4*)&ys[kk * 132 + tx * 8];
            float4 yv1 = *(const float4*)&ys[kk * 132 + tx * 8 + 4];
            float xr[8] = {xv0.x, xv0.y, xv0.z, xv0.w, xv1.x, xv1.y, xv1.z, xv1.w};
            float yr[8] = {yv0.x, yv0.y, yv0.z, yv0.w, yv1.x, yv1.y, yv1.z, yv1.w};
            #pragma unroll
            for (int r = 0; r < 8; r++)
                #pragma unroll
                for (int s = 0; s < 8; s++)
                    acc[r][s] = fmaf(xr[r], yr[s], acc[r][s]);
        }
    }

    float x2[8], y2[8];
    #pragma unroll
    for (int r = 0; r < 8; r++) x2[r] = g_nx[b * TT + I0 + ty * 8 + r];
    #pragma unroll
    for (int s = 0; s < 8; s++) y2[s] = g_ny[b * TT + J0 + tx * 8 + s];

    #pragma unroll
    for (int ph = 0; ph < 2; ph++) {
        __syncthreads();
        if ((ty >> 3) == ph) {
            int rl = (ty & 7) * 8;
            #pragma unroll
            for (int r = 0; r < 8; r++) {
                float4 o0, o1;
                o0.x = fmaf(-2.f, acc[r][0], x2[r] + y2[0]);
                o0.y = fmaf(-2.f, acc[r][1], x2[r] + y2[1]);
                o0.z = fmaf(-2.f, acc[r][2], x2[r] + y2[2]);
                o0.w = fmaf(-2.f, acc[r][3], x2[r] + y2[3]);
                o1.x = fmaf(-2.f, acc[r][4], x2[r] + y2[4]);
                o1.y = fmaf(-2.f, acc[r][5], x2[r] + y2[5]);
                o1.z = fmaf(-2.f, acc[r][6], x2[r] + y2[6]);
                o1.w = fmaf(-2.f, acc[r][7], x2[r] + y2[7]);
                *(float4*)&sbuf[(rl + r) * PITCH + tx * 8] = o0;
                *(float4*)&sbuf[(rl + r) * PITCH + tx * 8 + 4] = o1;
            }
        }
        __syncthreads();
        int Dlo = ph * 64, Dhi = ph * 64 + 190;
        for (int D = Dlo + w; D <= Dhi; D += 8) {
            int rlo = ph * 64;      if (D - 127 > rlo) rlo = D - 127;
            int rhi = ph * 64 + 63; if (D < rhi) rhi = D;
            int len = rhi - rlo + 1;
            if (len <= 0) continue;
            int rr = I0 + J0 + D;                 // global slab row
            size_t ebase = (((size_t)b << 20) + ((size_t)(rr >> 1) << 10)
                            + (size_t)(I0 + rlo)) * 2 + (rr & 1);
            int sb = (rlo - ph * 64) * PITCH + (D - rlo);
            for (int k = lane; k < len; k += 32)
                g_costh[ebase + 2 * (size_t)k] =
                    __float2half_rn(sbuf[sb + k * (PITCH - 1)]);
        }
    }
}

// ---------------------------------------------------------------------------
// Kernel 2: soft-DTW wavefront, warp-skewed rounds (1 barrier / 4 diagonals).
// fp16 pair-interleaved cost: ONE float4 load per thread covers 2 diagonals
// x 4 rows; 2 loads/round, triple-buffered 2 rounds ahead, L2-resident slab.
// ---------------------------------------------------------------------------
__device__ __forceinline__ void cell_fast(float a, float up, float dg, float cv,
                                          bool v, float& nr, bool& need) {
    float lo = fminf(a, up), hi = fmaxf(a, up);
    float m = fminf(lo, dg);
    float med = fminf(hi, fmaxf(lo, dg));
    need = v && ((med - m) < GAPT);
    nr = v ? (cv + m) : BIGF;
}
__device__ __forceinline__ void cell_exact(float a, float up, float dg, float cv,
                                           bool v, float& nr) {
    float lo = fminf(a, up), hi = fmaxf(a, up);
    float m = fminf(lo, dg);
    float med = fminf(hi, fmaxf(lo, dg));
    float mx = fmaxf(hi, dg);
    float e = 1.f + ex2f((m - med) * KS) + ex2f((m - mx) * KS);
    float r = cv + m - GLN2 * lg2f(e);
    nr = v ? r : BIGF;
}

__global__ __launch_bounds__(256) void dp_kernel() {
    const int b = blockIdx.x;
    const int tid = threadIdx.x;
    const int w = tid >> 5;
    const int lane = tid & 31;

    __shared__ float s_edge[8][16];   // per-warp edge ring, slot = diag & 15
    if (tid < 128) ((float*)s_edge)[tid] = BIGF;
    __syncthreads();

    const int I = 4 * tid + 1;                    // first row (1-based)
    // halves base for this thread's 4 rows: element ((b<<20)+(p<<10)+4tid)*2
    const __half* baseh = g_costh + ((size_t)b << 21) + 8 * (size_t)tid;
    // pair p covers slab rows 2p,2p+1 i.e. diagonals d = 2p+2, 2p+3

    float rp0 = BIGF, rp1 = BIGF, rp2 = BIGF, rp3 = BIGF;
    float qp0 = BIGF, qp1 = BIGF, qp2 = BIGF, qp3 = BIGF;
    // pu = previous diagonal's post-override u_sh; seeds R[0][0]=0 at d=2
    float pu = (w == 0 && lane == 0) ? 0.f : BIGF;

    const int wlo = 128 * w + 2;
    const int whi = 128 * w + 128 + TT;           // w=7 -> exactly 2048

    float4 cur[2], nxt[2];
    #pragma unroll
    for (int k = 0; k < 2; k++)
        cur[k] = *(const float4*)(baseh + ((size_t)k << 11));        // pairs 0,1
    #pragma unroll
    for (int k = 0; k < 2; k++)
        nxt[k] = *(const float4*)(baseh + ((size_t)(2 + k) << 11));  // pairs 2,3

    int rw = -w;   // r - w
    for (int r = 0; r < 519; ++r, ++rw) {
        if (rw >= 0) {
            int D = 4 * rw + 2;   // this warp's first diagonal this round
            // prefetch pairs for round r+2: 2*rw+4, 2*rw+5 (clamped)
            float4 nn[2];
            #pragma unroll
            for (int k = 0; k < 2; k++) {
                int p = 2 * rw + 4 + k;
                if (p > 1023) p = 1023;
                nn[k] = *(const float4*)(baseh + ((size_t)p << 11));
            }

            if (D <= whi && D + 3 >= wlo) {
                #pragma unroll
                for (int k = 0; k < 4; k++) {
                    int d = D + k;
                    bool act = (d >= wlo) && (d <= whi);
                    float u_sh = __shfl_up_sync(0xFFFFFFFFu, rp3, 1);
                    if (lane == 0)
                        u_sh = (w == 0) ? BIGF : s_edge[w - 1][(d - 1) & 15];
                    float g_sh = pu;
                    pu = u_sh;

                    // cost values for this diagonal: half2 lane e = k&1
                    const __half2* hp = (const __half2*)(&cur[k >> 1]);
                    float c0 = (k & 1) ? __high2float(hp[0]) : __low2float(hp[0]);
                    float c1 = (k & 1) ? __high2float(hp[1]) : __low2float(hp[1]);
                    float c2 = (k & 1) ? __high2float(hp[2]) : __low2float(hp[2]);
                    float c3 = (k & 1) ? __high2float(hp[3]) : __low2float(hp[3]);

                    int jm1 = d - I - 1;
                    float nr0, nr1, nr2, nr3;
                    bool n0 = false, n1 = false, n2 = false, n3 = false;
                    if (act) {
                        cell_fast(rp0, u_sh, g_sh, c0, (unsigned)jm1 < 1024u, nr0, n0);
                        cell_fast(rp1, rp0, qp0, c1, (unsigned)(jm1 - 1) < 1024u, nr1, n1);
                        cell_fast(rp2, rp1, qp1, c2, (unsigned)(jm1 - 2) < 1024u, nr2, n2);
                        cell_fast(rp3, rp2, qp2, c3, (unsigned)(jm1 - 3) < 1024u, nr3, n3);
                    }
                    if (__any_sync(0xFFFFFFFFu, (n0 | n1 | n2 | n3))) {
                        if (act) {   // warp-uniform; exact recompute of all 4 cells
                            cell_exact(rp0, u_sh, g_sh, c0, (unsigned)jm1 < 1024u, nr0);
                            cell_exact(rp1, rp0, qp0, c1, (unsigned)(jm1 - 1) < 1024u, nr1);
                            cell_exact(rp2, rp1, qp1, c2, (unsigned)(jm1 - 2) < 1024u, nr2);
                            cell_exact(rp3, rp2, qp2, c3, (unsigned)(jm1 - 3) < 1024u, nr3);
                        }
                    }
                    if (act) {
                        qp0 = rp0; qp1 = rp1; qp2 = rp2; qp3 = rp3;
                        rp0 = nr0; rp1 = nr1; rp2 = nr2; rp3 = nr3;
                    }
                    if (lane == 31) s_edge[w][d & 15] = rp3;
                }
            }

            #pragma unroll
            for (int k = 0; k < 2; k++) { cur[k] = nxt[k]; nxt[k] = nn[k]; }
        }
        __syncthreads();
    }

    if (tid == 255) g_partial[b] = rp3;   // R[T][T] (warp 7 ends at d=2048)
}

// ---------------------------------------------------------------------------
// Kernel 3: deterministic sum of the 16 per-batch distances.
// ---------------------------------------------------------------------------
__global__ void sum_kernel(float* out) {
    if (threadIdx.x == 0) {
        float s = 0.f;
        #pragma unroll
        for (int b = 0; b < BB; b++) s += g_partial[b];
        out[0] = s;
    }
}

extern "C" void kernel_launch(void* const* d_in, const int* in_sizes, int n_in,
                              void* d_out, int out_size) {
    const float* x = (const float*)d_in[0];
    const float* y = (const float*)d_in[1];
    float* out = (float*)d_out;

    norms_kernel<<<4096, 256>>>(x, y);
    cost_kernel<<<dim3(8, 8, BB), 256>>>(x, y);
    dp_kernel<<<BB, 256>>>();
    sum_kernel<<<1, 32>>>(out);
}

// round 10
// speedup vs baseline: 2.1178x; 2.1178x over previous
#include <cuda_runtime.h>
#include <cuda_fp16.h>
#include <cstddef>

#define TT 1024
#define BB 16
#define CC 64
#define BIGF 1e10f
// 1/(gamma*ln2), gamma = 0.01
#define KS 144.2695040888963f
// gamma*ln2
#define GLN2 0.006931471805599453f
// (med - min) threshold below which exp terms matter (16 / KS)
#define GAPT 0.11090354888959125f

// Scratch (device globals: allocation-free rule)
// fp16 diag-major cost: slab row rr = i+j-2 (0..2046), col = i-1 (0..1023).
__device__ __half g_costh[(size_t)BB * 2047 * 1024];   // 67 MB
__device__ float g_nx[BB * TT];
__device__ float g_ny[BB * TT];
__device__ float g_partial[BB];

__device__ __forceinline__ float ex2f(float x) {
    float y;
    asm("ex2.approx.ftz.f32 %0, %1;" : "=f"(y) : "f"(x));
    return y;
}
__device__ __forceinline__ float lg2f(float x) {
    float y;
    asm("lg2.approx.ftz.f32 %0, %1;" : "=f"(y) : "f"(x));
    return y;
}

// ---------------------------------------------------------------------------
// Kernel 0: row norms  ||x_i||^2, ||y_j||^2  (one warp per row)
// ---------------------------------------------------------------------------
__global__ void norms_kernel(const float* __restrict__ x,
                             const float* __restrict__ y) {
    int gwarp = (blockIdx.x * blockDim.x + threadIdx.x) >> 5;
    int lane = threadIdx.x & 31;
    const int nrows = BB * TT;
    if (gwarp >= 2 * nrows) return;
    const float* src = (gwarp < nrows) ? x : y;
    float* dst = (gwarp < nrows) ? g_nx : g_ny;
    int row = (gwarp < nrows) ? gwarp : (gwarp - nrows);
    float v0 = src[(size_t)row * CC + lane];
    float v1 = src[(size_t)row * CC + 32 + lane];
    float s = v0 * v0 + v1 * v1;
    #pragma unroll
    for (int o = 16; o; o >>= 1) s += __shfl_xor_sync(0xFFFFFFFFu, s, o);
    if (lane == 0) dst[row] = s;
}

// ---------------------------------------------------------------------------
// Kernel 1: cost tile 128x128 per CTA (8x8 regs/thread), then scatter the
// tile (fp16) to diag-major g_costh via smem. Scatter stores: 32 contiguous
// halves per warp iteration = 2 fully-covered 32B sectors (no RMW).
// ---------------------------------------------------------------------------
#define PITCH 132
__global__ __launch_bounds__(256) void cost_kernel(const float* __restrict__ x,
                                                   const float* __restrict__ y) {
    __shared__ float sbuf[8448];   // union: xs[32*132] + ys[32*132] | tile 64*132
    float* xs = sbuf;              // [kk][row] -> kk*132 + row
    float* ys = sbuf + 4224;

    int b = blockIdx.z;
    int I0 = blockIdx.y * 128;
    int J0 = blockIdx.x * 128;
    int tid = threadIdx.x;
    int tx = tid & 15;
    int ty = tid >> 4;
    int w = tid >> 5;
    int lane = tid & 31;

    const float* xb = x + ((size_t)b * TT + I0) * CC;
    const float* yb = y + ((size_t)b * TT + J0) * CC;

    float acc[8][8];
    #pragma unroll
    for (int r = 0; r < 8; r++)
        #pragma unroll
        for (int s = 0; s < 8; s++) acc[r][s] = 0.f;

    for (int k0 = 0; k0 < CC; k0 += 32) {
        __syncthreads();
        #pragma unroll
        for (int e = 0; e < 4096; e += 256) {
            int idx = e + tid;
            int row = idx >> 5;
            int kk = idx & 31;
            xs[kk * 132 + row] = xb[(size_t)row * CC + k0 + kk];
            ys[kk * 132 + row] = yb[(size_t)row * CC + k0 + kk];
        }
        __syncthreads();
        #pragma unroll
        for (int kk = 0; kk < 32; kk++) {
            float4 xv0 = *(const float4*)&xs[kk * 132 + ty * 8];
            float4 xv1 = *(const float4*)&xs[kk * 132 + ty * 8 + 4];
            float4 yv0 = *(const float4*)&ys[kk * 132 + tx * 8];
            float4 yv1 = *(const float4*)&ys[kk * 132 + tx * 8 + 4];
            float xr[8] = {xv0.x, xv0.y, xv0.z, xv0.w, xv1.x, xv1.y, xv1.z, xv1.w};
            float yr[8] = {yv0.x, yv0.y, yv0.z, yv0.w, yv1.x, yv1.y, yv1.z, yv1.w};
            #pragma unroll
            for (int r = 0; r < 8; r++)
                #pragma unroll
                for (int s = 0; s < 8; s++)
                    acc[r][s] = fmaf(xr[r], yr[s], acc[r][s]);
        }
    }

    float x2[8], y2[8];
    #pragma unroll
    for (int r = 0; r < 8; r++) x2[r] = g_nx[b * TT + I0 + ty * 8 + r];
    #pragma unroll
    for (int s = 0; s < 8; s++) y2[s] = g_ny[b * TT + J0 + tx * 8 + s];

    __half* slab = g_costh + (size_t)b * 2047 * 1024;

    #pragma unroll
    for (int ph = 0; ph < 2; ph++) {
        __syncthreads();
        if ((ty >> 3) == ph) {
            int rl = (ty & 7) * 8;
            #pragma unroll
            for (int r = 0; r < 8; r++) {
                float4 o0, o1;
                o0.x = fmaf(-2.f, acc[r][0], x2[r] + y2[0]);
                o0.y = fmaf(-2.f, acc[r][1], x2[r] + y2[1]);
                o0.z = fmaf(-2.f, acc[r][2], x2[r] + y2[2]);
                o0.w = fmaf(-2.f, acc[r][3], x2[r] + y2[3]);
                o1.x = fmaf(-2.f, acc[r][4], x2[r] + y2[4]);
                o1.y = fmaf(-2.f, acc[r][5], x2[r] + y2[5]);
                o1.z = fmaf(-2.f, acc[r][6], x2[r] + y2[6]);
                o1.w = fmaf(-2.f, acc[r][7], x2[r] + y2[7]);
                *(float4*)&sbuf[(rl + r) * PITCH + tx * 8] = o0;
                *(float4*)&sbuf[(rl + r) * PITCH + tx * 8 + 4] = o1;
            }
        }
        __syncthreads();
        int Dlo = ph * 64, Dhi = ph * 64 + 190;
        for (int D = Dlo + w; D <= Dhi; D += 8) {
            int rlo = ph * 64;      if (D - 127 > rlo) rlo = D - 127;
            int rhi = ph * 64 + 63; if (D < rhi) rhi = D;
            int len = rhi - rlo + 1;
            if (len <= 0) continue;
            int rr = I0 + J0 + D;                 // global slab row
            __half* gout = slab + (size_t)rr * 1024 + I0 + rlo;
            int sb = (rlo - ph * 64) * PITCH + (D - rlo);
            for (int k = lane; k < len; k += 32)
                gout[k] = __float2half_rn(sbuf[sb + k * (PITCH - 1)]);
        }
    }
}

// ---------------------------------------------------------------------------
// Kernel 2: soft-DTW wavefront, warp-skewed rounds (1 barrier / 4 diagonals).
// fp16 diag-major cost, 8B (uint2) load per thread per diagonal, prefetched
// THREE rounds ahead (12 outstanding loads/thread); slab is L2-resident.
// ---------------------------------------------------------------------------
__device__ __forceinline__ void cell_fast(float a, float up, float dg, float cv,
                                          bool v, float& nr, bool& need) {
    float lo = fminf(a, up), hi = fmaxf(a, up);
    float m = fminf(lo, dg);
    float med = fminf(hi, fmaxf(lo, dg));
    need = v && ((med - m) < GAPT);
    nr = v ? (cv + m) : BIGF;
}
__device__ __forceinline__ void cell_exact(float a, float up, float dg, float cv,
                                           bool v, float& nr) {
    float lo = fminf(a, up), hi = fmaxf(a, up);
    float m = fminf(lo, dg);
    float med = fminf(hi, fmaxf(lo, dg));
    float mx = fmaxf(hi, dg);
    float e = 1.f + ex2f((m - med) * KS) + ex2f((m - mx) * KS);
    float r = cv + m - GLN2 * lg2f(e);
    nr = v ? r : BIGF;
}

__global__ __launch_bounds__(256) void dp_kernel() {
    const int b = blockIdx.x;
    const int tid = threadIdx.x;
    const int w = tid >> 5;
    const int lane = tid & 31;

    __shared__ float s_edge[8][16];   // per-warp edge ring, slot = diag & 15
    if (tid < 128) ((float*)s_edge)[tid] = BIGF;
    __syncthreads();

    const int I = 4 * tid + 1;                    // first row (1-based)
    // this thread's 4 columns start at half index 4*tid within each slab row
    const __half* baseh = g_costh + (size_t)b * 2047 * 1024 + 4 * (size_t)tid;
    // slab row for diagonal d is (d-2); rows valid 0..2046, stride 1024 halves

    float rp0 = BIGF, rp1 = BIGF, rp2 = BIGF, rp3 = BIGF;
    float qp0 = BIGF, qp1 = BIGF, qp2 = BIGF, qp3 = BIGF;
    // pu = previous diagonal's post-override u_sh; seeds R[0][0]=0 at d=2
    float pu = (w == 0 && lane == 0) ? 0.f : BIGF;

    const int wlo = 128 * w + 2;
    const int whi = 128 * w + 128 + TT;           // w=7 -> exactly 2048

    // prefetch queues: q0 = this round, q1 = +1, q2 = +2 (rows 4*rw'+k)
    uint2 q0[4], q1[4], q2[4];
    #pragma unroll
    for (int k = 0; k < 4; k++) {
        q0[k] = *(const uint2*)(baseh + (size_t)(0 + k) * 1024);
        q1[k] = *(const uint2*)(baseh + (size_t)(4 + k) * 1024);
        q2[k] = *(const uint2*)(baseh + (size_t)(8 + k) * 1024);
    }

    int rw = -w;   // r - w
    for (int r = 0; r < 519; ++r, ++rw) {
        if (rw >= 0) {
            int D = 4 * rw + 2;   // this warp's first diagonal this round
            // prefetch rows for round rw+3: 4*rw+12 .. +15 (clamped)
            uint2 nn[4];
            #pragma unroll
            for (int k = 0; k < 4; k++) {
                int ri = 4 * rw + 12 + k;
                if (ri > 2046) ri = 2046;
                nn[k] = *(const uint2*)(baseh + (size_t)ri * 1024);
            }

            if (D <= whi && D + 3 >= wlo) {
                #pragma unroll
                for (int k = 0; k < 4; k++) {
                    int d = D + k;
                    bool act = (d >= wlo) && (d <= whi);
                    float u_sh = __shfl_up_sync(0xFFFFFFFFu, rp3, 1);
                    if (lane == 0)
                        u_sh = (w == 0) ? BIGF : s_edge[w - 1][(d - 1) & 15];
                    float g_sh = pu;
                    pu = u_sh;

                    // cost values: 4 halves = columns 4tid..4tid+3 of row d-2
                    __half2 hlo = *(__half2*)&q0[k].x;
                    __half2 hhi = *(__half2*)&q0[k].y;
                    float c0 = __low2float(hlo);
                    float c1 = __high2float(hlo);
                    float c2 = __low2float(hhi);
                    float c3 = __high2float(hhi);

                    int jm1 = d - I - 1;
                    float nr0, nr1, nr2, nr3;
                    bool n0 = false, n1 = false, n2 = false, n3 = false;
                    if (act) {
                        cell_fast(rp0, u_sh, g_sh, c0, (unsigned)jm1 < 1024u, nr0, n0);
                        cell_fast(rp1, rp0, qp0, c1, (unsigned)(jm1 - 1) < 1024u, nr1, n1);
                        cell_fast(rp2, rp1, qp1, c2, (unsigned)(jm1 - 2) < 1024u, nr2, n2);
                        cell_fast(rp3, rp2, qp2, c3, (unsigned)(jm1 - 3) < 1024u, nr3, n3);
                    }
                    if (__any_sync(0xFFFFFFFFu, (n0 | n1 | n2 | n3))) {
                        if (act) {   // warp-uniform; exact recompute of all 4 cells
                            cell_exact(rp0, u_sh, g_sh, c0, (unsigned)jm1 < 1024u, nr0);
                            cell_exact(rp1, rp0, qp0, c1, (unsigned)(jm1 - 1) < 1024u, nr1);
                            cell_exact(rp2, rp1, qp1, c2, (unsigned)(jm1 - 2) < 1024u, nr2);
                            cell_exact(rp3, rp2, qp2, c3, (unsigned)(jm1 - 3) < 1024u, nr3);
                        }
                    }
                    if (act) {
                        qp0 = rp0; qp1 = rp1; qp2 = rp2; qp3 = rp3;
                        rp0 = nr0; rp1 = nr1; rp2 = nr2; rp3 = nr3;
                    }
                    if (lane == 31) s_edge[w][d & 15] = rp3;
                }
            }

            #pragma unroll
            for (int k = 0; k < 4; k++) { q0[k] = q1[k]; q1[k] = q2[k]; q2[k] = nn[k]; }
        }
        __syncthreads();
    }

    if (tid == 255) g_partial[b] = rp3;   // R[T][T] (warp 7 ends at d=2048)
}

// ---------------------------------------------------------------------------
// Kernel 3: deterministic sum of the 16 per-batch distances.
// ---------------------------------------------------------------------------
__global__ void sum_kernel(float* out) {
    if (threadIdx.x == 0) {
        float s = 0.f;
        #pragma unroll
        for (int b = 0; b < BB; b++) s += g_partial[b];
        out[0] = s;
    }
}

extern "C" void kernel_launch(void* const* d_in, const int* in_sizes, int n_in,
                              void* d_out, int out_size) {
    const float* x = (const float*)d_in[0];
    const float* y = (const float*)d_in[1];
    float* out = (float*)d_out;

    norms_kernel<<<4096, 256>>>(x, y);
    cost_kernel<<<dim3(8, 8, BB), 256>>>(x, y);
    dp_kernel<<<BB, 256>>>();
    sum_kernel<<<1, 32>>>(out);
}